// round 3
// baseline (speedup 1.0000x reference)
#include <cuda_runtime.h>

#define IC1 10
#define OC1 64
#define OC2 128
#define NB  64          // 2 images x 32 batch

__device__ int   g_cnt[NB][OC1][9];    // S, Rf, Rl, Cf, Cl, q_tl, q_tr, q_bl, q_br
__device__ float g_s2[NB][OC2];
__device__ float g_inv1[OC1],  g_beta1[OC1];
__device__ float g_inv2[OC2],  g_beta2[OC2];
__device__ float g_U[OC1][IC1][16];    // Winograd F(2x2,3x3) transformed weights

// dynamic shared layout (floats)
#define SM_SC   0        // int sc[5][64]           -> 320
#define SM_IN   320      // staged input tile 18x34 -> 616 (612 used)
#define SM_U    936      // U half: 32*10*16        -> 5120  (16B aligned: 936*4=3744)
#define SM_V    6056     // V: [10][8][128] float2  -> 20480 floats (8B aligned)
#define SM_FLOATS 26536
#define SM_BYTES  (SM_FLOATS * 4)   // 106144 B -> 2 blocks/SM

// ---------------------------------------------------------------------------
// prep: zero counters, fold BN params, Winograd weight transform
// ---------------------------------------------------------------------------
__global__ void prep_kernel(const float* __restrict__ w1,
                            const float* __restrict__ g1, const float* __restrict__ b1,
                            const float* __restrict__ m1, const float* __restrict__ v1,
                            const float* __restrict__ g2, const float* __restrict__ b2,
                            const float* __restrict__ m2, const float* __restrict__ v2) {
    int gid = blockIdx.x * blockDim.x + threadIdx.x;
    int* c = &g_cnt[0][0][0];
    for (int i = gid; i < NB * OC1 * 9; i += gridDim.x * blockDim.x) c[i] = 0;
    if (blockIdx.x == 0) {
        int t = threadIdx.x;
        if (t < OC1) {
            float inv = g1[t] / sqrtf(v1[t] + 1e-5f);
            g_inv1[t] = inv;
            g_beta1[t] = b1[t] - m1[t] * inv;
        }
        if (t < OC2) {
            float inv = g2[t] / sqrtf(v2[t] + 1e-5f);
            g_inv2[t] = inv;
            g_beta2[t] = b2[t] - m2[t] * inv;
        }
    }
    // Winograd weight transform U = G g G^T for each (oc, ic)
    if (gid < OC1 * IC1) {
        int oc = gid / IC1, ic = gid % IC1;
        const float* g = w1 + (oc * IC1 + ic) * 9;
        float gg[4][3];
#pragma unroll
        for (int cix = 0; cix < 3; ++cix) {
            float a = g[cix], b = g[3 + cix], d = g[6 + cix];
            gg[0][cix] = a;
            gg[1][cix] = 0.5f * (a + b + d);
            gg[2][cix] = 0.5f * (a - b + d);
            gg[3][cix] = d;
        }
        float* U = &g_U[oc][ic][0];
#pragma unroll
        for (int r = 0; r < 4; ++r) {
            float a = gg[r][0], b = gg[r][1], d = gg[r][2];
            U[r * 4 + 0] = a;
            U[r * 4 + 1] = 0.5f * (a + b + d);
            U[r * 4 + 2] = 0.5f * (a - b + d);
            U[r * 4 + 3] = d;
        }
    }
}

// ---------------------------------------------------------------------------
// stage A: Winograd conv1 + BN + maxpool2 + spike + 9-aggregate reduction
// grid (8, 16, 64), block 128; each thread owns one pooled output (= one
// Winograd F(2x2,3x3) tile) for all 64 output channels.
// ---------------------------------------------------------------------------
__global__ __launch_bounds__(128, 2) void stageA_kernel(const float* __restrict__ x0,
                                                        const float* __restrict__ x1) {
    extern __shared__ float smem[];
    int*    sc  = (int*)&smem[SM_SC];
    float*  sin = &smem[SM_IN];
    float4* sU4 = (float4*)&smem[SM_U];
    float2* sV2 = (float2*)&smem[SM_V];

    const int tid = threadIdx.x;
    const int bx = blockIdx.x, by = blockIdx.y, n = blockIdx.z;
    const float* __restrict__ x = (n < 32) ? x0 : x1;
    const int b = n & 31;

    for (int i = tid; i < 5 * OC1; i += 128) sc[i] = 0;
    // U half 0 (oc 0..31): 5120 floats = 1280 float4
    {
        const float4* gU4 = (const float4*)&g_U[0][0][0];
        for (int i = tid; i < 1280; i += 128) sU4[i] = __ldg(&gU4[i]);
    }

    const int lpx = tid & 15, lpy = tid >> 4;
    const int gpy = by * 8 + lpy, gpx = bx * 16 + lpx;
    const int lane = tid & 31;
    const bool edge = (by == 0) | (by == 15) | (bx == 0) | (bx == 7);
    const int rr = 2 * lpy, cc = 2 * lpx;
    const int iy0 = by * 16 - 1;     // input row origin of this block's region
    const int ix0 = bx * 32 - 1;

    // ---- phase 1: per-ic input staging + Winograd input transform ----
    for (int ic = 0; ic < IC1; ++ic) {
        __syncthreads();
        for (int i = tid; i < 612; i += 128) {
            int rw = i / 34, cl = i % 34;
            int gy = iy0 + rw, gx = ix0 + cl;
            float v = 0.f;
            if ((unsigned)gy < 256u && (unsigned)gx < 256u)
                v = __ldg(&x[((b * IC1 + ic) * 256 + gy) * 256 + gx]);
            sin[i] = v;
        }
        __syncthreads();

        float d[4][4];
#pragma unroll
        for (int i = 0; i < 4; ++i) {
            const float2* p = (const float2*)&sin[(rr + i) * 34 + cc];
            float2 u = p[0], w = p[1];
            d[i][0] = u.x; d[i][1] = u.y; d[i][2] = w.x; d[i][3] = w.y;
        }
        float t[4][4];
#pragma unroll
        for (int cix = 0; cix < 4; ++cix) {
            t[0][cix] = d[0][cix] - d[2][cix];
            t[1][cix] = d[1][cix] + d[2][cix];
            t[2][cix] = d[2][cix] - d[1][cix];
            t[3][cix] = d[1][cix] - d[3][cix];
        }
#pragma unroll
        for (int r = 0; r < 4; ++r) {
            float v0 = t[r][0] - t[r][2];
            float v1 = t[r][1] + t[r][2];
            float v2 = t[r][2] - t[r][1];
            float v3 = t[r][1] - t[r][3];
            sV2[(ic * 8 + r * 2 + 0) * 128 + tid] = make_float2(v0, v1);
            sV2[(ic * 8 + r * 2 + 1) * 128 + tid] = make_float2(v2, v3);
        }
    }
    __syncthreads();

    // ---- phase 2: per-oc elementwise mul + output transform + epilogue ----
    for (int h = 0; h < 2; ++h) {
        if (h == 1) {
            __syncthreads();
            const float4* gU4 = (const float4*)&g_U[32][0][0];
            for (int i = tid; i < 1280; i += 128) sU4[i] = __ldg(&gU4[i]);
            __syncthreads();
        }
        for (int o = 0; o < 32; ++o) {
            const int oc = h * 32 + o;
            float M[16];
#pragma unroll
            for (int j = 0; j < 16; ++j) M[j] = 0.f;

#pragma unroll
            for (int ic = 0; ic < IC1; ++ic) {
                float4 u0 = sU4[(o * IC1 + ic) * 4 + 0];
                float4 u1 = sU4[(o * IC1 + ic) * 4 + 1];
                float4 u2 = sU4[(o * IC1 + ic) * 4 + 2];
                float4 u3 = sU4[(o * IC1 + ic) * 4 + 3];
                float2 v0 = sV2[(ic * 8 + 0) * 128 + tid];
                float2 v1 = sV2[(ic * 8 + 1) * 128 + tid];
                float2 v2 = sV2[(ic * 8 + 2) * 128 + tid];
                float2 v3 = sV2[(ic * 8 + 3) * 128 + tid];
                float2 v4 = sV2[(ic * 8 + 4) * 128 + tid];
                float2 v5 = sV2[(ic * 8 + 5) * 128 + tid];
                float2 v6 = sV2[(ic * 8 + 6) * 128 + tid];
                float2 v7 = sV2[(ic * 8 + 7) * 128 + tid];
                M[0]  = fmaf(u0.x, v0.x, M[0]);
                M[1]  = fmaf(u0.y, v0.y, M[1]);
                M[2]  = fmaf(u0.z, v1.x, M[2]);
                M[3]  = fmaf(u0.w, v1.y, M[3]);
                M[4]  = fmaf(u1.x, v2.x, M[4]);
                M[5]  = fmaf(u1.y, v2.y, M[5]);
                M[6]  = fmaf(u1.z, v3.x, M[6]);
                M[7]  = fmaf(u1.w, v3.y, M[7]);
                M[8]  = fmaf(u2.x, v4.x, M[8]);
                M[9]  = fmaf(u2.y, v4.y, M[9]);
                M[10] = fmaf(u2.z, v5.x, M[10]);
                M[11] = fmaf(u2.w, v5.y, M[11]);
                M[12] = fmaf(u3.x, v6.x, M[12]);
                M[13] = fmaf(u3.y, v6.y, M[13]);
                M[14] = fmaf(u3.z, v7.x, M[14]);
                M[15] = fmaf(u3.w, v7.y, M[15]);
            }
            // output transform Y = A^T M A
            float q0[4], q1[4];
#pragma unroll
            for (int cix = 0; cix < 4; ++cix) {
                q0[cix] = M[cix] + M[4 + cix] + M[8 + cix];
                q1[cix] = M[4 + cix] - M[8 + cix] - M[12 + cix];
            }
            float y00 = q0[0] + q0[1] + q0[2];
            float y01 = q0[1] - q0[2] - q0[3];
            float y10 = q1[0] + q1[1] + q1[2];
            float y11 = q1[1] - q1[2] - q1[3];

            float inv = __ldg(&g_inv1[oc]);
            float bet = __ldg(&g_beta1[oc]);
            float mx = fmaxf(fmaxf(y00, y01), fmaxf(y10, y11));
            float mn = fminf(fminf(y00, y01), fminf(y10, y11));
            float z = (inv >= 0.f ? mx : mn) * inv + bet;
            bool sp = z > 1.0f;
            unsigned bal = __ballot_sync(0xffffffffu, sp);
            if (lane == 0 && bal) atomicAdd(&sc[0 * OC1 + oc], __popc(bal));
            if (edge) {
                unsigned bR0 = __ballot_sync(0xffffffffu, sp && (gpy == 0));
                unsigned bR1 = __ballot_sync(0xffffffffu, sp && (gpy == 127));
                unsigned bC0 = __ballot_sync(0xffffffffu, sp && (gpx == 0));
                unsigned bC1 = __ballot_sync(0xffffffffu, sp && (gpx == 127));
                if (lane == 0) {
                    if (bR0) atomicAdd(&sc[1 * OC1 + oc], __popc(bR0));
                    if (bR1) atomicAdd(&sc[2 * OC1 + oc], __popc(bR1));
                    if (bC0) atomicAdd(&sc[3 * OC1 + oc], __popc(bC0));
                    if (bC1) atomicAdd(&sc[4 * OC1 + oc], __popc(bC1));
                }
                if (sp) {  // corner bits (unique writer per corner; pre-zeroed)
                    if (gpy == 0   && gpx == 0)        g_cnt[n][oc][5] = 1;
                    else if (gpy == 0   && gpx == 127) g_cnt[n][oc][6] = 1;
                    else if (gpy == 127 && gpx == 0)   g_cnt[n][oc][7] = 1;
                    else if (gpy == 127 && gpx == 127) g_cnt[n][oc][8] = 1;
                }
            }
        }
    }
    __syncthreads();
    if (tid < OC1) {
#pragma unroll
        for (int j = 0; j < 5; ++j) {
            int v = sc[j * OC1 + tid];
            if (v) atomicAdd(&g_cnt[n][tid][j], v);
        }
    }
}

// ---------------------------------------------------------------------------
// stage B: analytic conv2-mean via T aggregates, BN2, spike -> g_s2
// ---------------------------------------------------------------------------
__global__ __launch_bounds__(256) void stageB_kernel(const float* __restrict__ w2) {
    __shared__ __align__(16) float sT[OC1 * 9];
    const int n = blockIdx.x, tid = threadIdx.x;
    const int lane = tid & 31, warp = tid >> 5;
    if (tid < OC1) {
        const int* c = g_cnt[n][tid];
        int S = c[0], Rf = c[1], Rl = c[2], Cf = c[3], Cl = c[4];
        int Re[3] = {Rl, 0, Rf};
        int Ce[3] = {Cl, 0, Cf};
        int Q[9]  = {c[8], 0, c[7],  0, 0, 0,  c[6], 0, c[5]};
#pragma unroll
        for (int k = 0; k < 9; ++k)
            sT[tid * 9 + k] = (float)(S - Re[k / 3] - Ce[k % 3] + Q[k]);
    }
    __syncthreads();
#pragma unroll 1
    for (int i = 0; i < 16; ++i) {
        const int o = warp * 16 + i;
        const float* wr = w2 + o * 576;
        float acc = 0.f;
#pragma unroll
        for (int t = 0; t < 18; ++t) {
            int j = t * 32 + lane;
            acc = fmaf(__ldg(&wr[j]), sT[j], acc);
        }
#pragma unroll
        for (int s = 16; s; s >>= 1) acc += __shfl_xor_sync(0xffffffffu, acc, s);
        if (lane == 0) {
            float z = acc * (1.f / 16384.f);
            z = z * g_inv2[o] + g_beta2[o];
            g_s2[n][o] = (z > 1.f) ? 1.f : 0.f;
        }
    }
}

// ---------------------------------------------------------------------------
// stage C: feat = |s0 - s1|, fc1+relu, fc2  -> out (32,5)
// ---------------------------------------------------------------------------
__global__ __launch_bounds__(256) void stageC_kernel(const float* __restrict__ fc1w,
                                                     const float* __restrict__ fc1b,
                                                     const float* __restrict__ fc2w,
                                                     const float* __restrict__ fc2b,
                                                     float* __restrict__ out) {
    __shared__ float f[128];
    __shared__ float h[64];
    const int n = blockIdx.x, tid = threadIdx.x;
    const int lane = tid & 31, warp = tid >> 5;
    if (tid < 128) f[tid] = fabsf(g_s2[n][tid] - g_s2[n + 32][tid]);
    __syncthreads();
#pragma unroll 1
    for (int i = 0; i < 8; ++i) {
        const int k = warp * 8 + i;
        const float* wr = fc1w + k * 128;
        float acc = 0.f;
#pragma unroll
        for (int t = 0; t < 4; ++t) {
            int j = t * 32 + lane;
            acc = fmaf(__ldg(&wr[j]), f[j], acc);
        }
#pragma unroll
        for (int s = 16; s; s >>= 1) acc += __shfl_xor_sync(0xffffffffu, acc, s);
        if (lane == 0) h[k] = fmaxf(acc + fc1b[k], 0.f);
    }
    __syncthreads();
    if (warp == 0) {
#pragma unroll 1
        for (int c = 0; c < 5; ++c) {
            const float* wr = fc2w + c * 64;
            float acc = fmaf(__ldg(&wr[lane]), h[lane], 0.f);
            acc = fmaf(__ldg(&wr[lane + 32]), h[lane + 32], acc);
#pragma unroll
            for (int s = 16; s; s >>= 1) acc += __shfl_xor_sync(0xffffffffu, acc, s);
            if (lane == 0) out[n * 5 + c] = acc + fc2b[c];
        }
    }
}

extern "C" void kernel_launch(void* const* d_in, const int* in_sizes, int n_in,
                              void* d_out, int out_size) {
    const float* x0   = (const float*)d_in[0];
    const float* x1   = (const float*)d_in[1];
    const float* w1   = (const float*)d_in[2];
    const float* b1g  = (const float*)d_in[3];
    const float* b1b  = (const float*)d_in[4];
    const float* b1m  = (const float*)d_in[5];
    const float* b1v  = (const float*)d_in[6];
    const float* w2   = (const float*)d_in[7];
    const float* b2g  = (const float*)d_in[8];
    const float* b2b  = (const float*)d_in[9];
    const float* b2m  = (const float*)d_in[10];
    const float* b2v  = (const float*)d_in[11];
    const float* fc1w = (const float*)d_in[12];
    const float* fc1b = (const float*)d_in[13];
    const float* fc2w = (const float*)d_in[14];
    const float* fc2b = (const float*)d_in[15];

    cudaFuncSetAttribute(stageA_kernel,
                         cudaFuncAttributeMaxDynamicSharedMemorySize, SM_BYTES);

    prep_kernel<<<32, 256>>>(w1, b1g, b1b, b1m, b1v, b2g, b2b, b2m, b2v);
    dim3 gridA(8, 16, 64);
    stageA_kernel<<<gridA, 128, SM_BYTES>>>(x0, x1);
    stageB_kernel<<<64, 256>>>(w2);
    stageC_kernel<<<32, 256>>>(fc1w, fc1b, fc2w, fc2b, (float*)d_out);
}

// round 4
// speedup vs baseline: 2.0278x; 2.0278x over previous
#include <cuda_runtime.h>

#define IC1 10
#define OC1 64
#define OC2 128
#define NB  64          // 2 images x 32 batch

__device__ int   g_cnt[NB][OC1][9];    // S, Rf, Rl, Cf, Cl, q_tl, q_tr, q_bl, q_br
__device__ float g_s2[NB][OC2];
__device__ float g_inv1[OC1],  g_beta1[OC1];
__device__ float g_inv2[OC2],  g_beta2[OC2];
__device__ float g_U[OC1][IC1][16];    // Winograd F(2x2,3x3) transformed weights

// packed fp32x2 (FFMA2) helpers
#define FMA_X2(d, a, b, c) \
    asm("fma.rn.f32x2 %0, %1, %2, %3;" : "=l"(d) : "l"(a), "l"(b), "l"(c))
#define PACK2(d, lo, hi) \
    asm("mov.b64 %0, {%1, %2};" : "=l"(d) : "r"(__float_as_uint(lo)), "r"(__float_as_uint(hi)))
#define UNPACK2(lo, hi, v) \
    asm("mov.b64 {%0, %1}, %2;" : "=r"(lo), "=r"(hi) : "l"(v))

// ---------------------------------------------------------------------------
// prep: zero counters, fold BN params, Winograd weight transform
// ---------------------------------------------------------------------------
__global__ void prep_kernel(const float* __restrict__ w1,
                            const float* __restrict__ g1, const float* __restrict__ b1,
                            const float* __restrict__ m1, const float* __restrict__ v1,
                            const float* __restrict__ g2, const float* __restrict__ b2,
                            const float* __restrict__ m2, const float* __restrict__ v2) {
    int gid = blockIdx.x * blockDim.x + threadIdx.x;
    int* c = &g_cnt[0][0][0];
    for (int i = gid; i < NB * OC1 * 9; i += gridDim.x * blockDim.x) c[i] = 0;
    if (blockIdx.x == 0) {
        int t = threadIdx.x;
        if (t < OC1) {
            float inv = g1[t] / sqrtf(v1[t] + 1e-5f);
            g_inv1[t] = inv;
            g_beta1[t] = b1[t] - m1[t] * inv;
        }
        if (t < OC2) {
            float inv = g2[t] / sqrtf(v2[t] + 1e-5f);
            g_inv2[t] = inv;
            g_beta2[t] = b2[t] - m2[t] * inv;
        }
    }
    if (gid < OC1 * IC1) {
        int oc = gid / IC1, ic = gid % IC1;
        const float* g = w1 + (oc * IC1 + ic) * 9;
        float gg[4][3];
#pragma unroll
        for (int cix = 0; cix < 3; ++cix) {
            float a = g[cix], b = g[3 + cix], d = g[6 + cix];
            gg[0][cix] = a;
            gg[1][cix] = 0.5f * (a + b + d);
            gg[2][cix] = 0.5f * (a - b + d);
            gg[3][cix] = d;
        }
        float* U = &g_U[oc][ic][0];
#pragma unroll
        for (int r = 0; r < 4; ++r) {
            float a = gg[r][0], b = gg[r][1], d = gg[r][2];
            U[r * 4 + 0] = a;
            U[r * 4 + 1] = 0.5f * (a + b + d);
            U[r * 4 + 2] = 0.5f * (a - b + d);
            U[r * 4 + 3] = d;
        }
    }
}

// ---------------------------------------------------------------------------
// stage A: Winograd conv1 (V in registers, FFMA2 over j-pairs) + BN + maxpool2
//          + spike + 9-aggregate reduction
// grid (8, 16, 64), block 128; one thread = one pooled output (= one F(2x2)
// tile) for all 64 output channels.
// ---------------------------------------------------------------------------
__global__ __launch_bounds__(128, 2) void stageA_kernel(const float* __restrict__ x0,
                                                        const float* __restrict__ x1) {
    __shared__ __align__(16) float sU[OC1 * IC1 * 16];   // 40960 B
    __shared__ __align__(16) float sin_[616];            //  2464 B (612 used)
    __shared__ int sc[5][OC1];                           //  1280 B  (total 44704)

    const int tid = threadIdx.x;
    const int bx = blockIdx.x, by = blockIdx.y, n = blockIdx.z;
    const float* __restrict__ x = (n < 32) ? x0 : x1;
    const int b = n & 31;

    // load all U: 10240 floats = 2560 float4
    {
        const float4* gU4 = (const float4*)&g_U[0][0][0];
        float4* sU4 = (float4*)sU;
        for (int i = tid; i < 2560; i += 128) sU4[i] = __ldg(&gU4[i]);
    }
    for (int i = tid; i < 5 * OC1; i += 128) ((int*)sc)[i] = 0;

    const int lpx = tid & 15, lpy = tid >> 4;
    const int gpy = by * 8 + lpy, gpx = bx * 16 + lpx;
    const int lane = tid & 31;
    const bool edge = (by == 0) | (by == 15) | (bx == 0) | (bx == 7);
    const int rr = 2 * lpy, cc = 2 * lpx;
    const int iy0 = by * 16 - 1;
    const int ix0 = bx * 32 - 1;

    // ---- phase 1: per-ic staging + input transform -> V registers ----
    unsigned long long Vp[IC1][8];   // j-pairs: (j, j+1) for even j
#pragma unroll
    for (int ic = 0; ic < IC1; ++ic) {
        __syncthreads();
#pragma unroll
        for (int u = 0; u < 5; ++u) {
            int i = tid + u * 128;
            if (i < 612) {
                int rw = i / 34, cl = i % 34;
                int gy = iy0 + rw, gx = ix0 + cl;
                float v = 0.f;
                if ((unsigned)gy < 256u && (unsigned)gx < 256u)
                    v = __ldg(&x[((b * IC1 + ic) * 256 + gy) * 256 + gx]);
                sin_[i] = v;
            }
        }
        __syncthreads();

        float d[4][4];
#pragma unroll
        for (int i = 0; i < 4; ++i) {
            const float2* p = (const float2*)&sin_[(rr + i) * 34 + cc];
            float2 u = p[0], w = p[1];
            d[i][0] = u.x; d[i][1] = u.y; d[i][2] = w.x; d[i][3] = w.y;
        }
        float t[4][4];
#pragma unroll
        for (int cix = 0; cix < 4; ++cix) {
            t[0][cix] = d[0][cix] - d[2][cix];
            t[1][cix] = d[1][cix] + d[2][cix];
            t[2][cix] = d[2][cix] - d[1][cix];
            t[3][cix] = d[1][cix] - d[3][cix];
        }
#pragma unroll
        for (int r = 0; r < 4; ++r) {
            float v0 = t[r][0] - t[r][2];
            float v1 = t[r][1] + t[r][2];
            float v2 = t[r][2] - t[r][1];
            float v3 = t[r][1] - t[r][3];
            PACK2(Vp[ic][r * 2 + 0], v0, v1);
            PACK2(Vp[ic][r * 2 + 1], v2, v3);
        }
    }
    __syncthreads();

    // ---- phase 2: per-oc FFMA2 accumulate + output transform + epilogue ----
#pragma unroll 1
    for (int oc = 0; oc < OC1; ++oc) {
        const ulonglong2* up = (const ulonglong2*)&sU[oc * IC1 * 16];
        unsigned long long M[8];
#pragma unroll
        for (int j = 0; j < 8; ++j) M[j] = 0ULL;

#pragma unroll
        for (int ic = 0; ic < IC1; ++ic) {
            ulonglong2 ua = up[ic * 4 + 0];
            ulonglong2 ub = up[ic * 4 + 1];
            ulonglong2 uc2 = up[ic * 4 + 2];
            ulonglong2 ud = up[ic * 4 + 3];
            FMA_X2(M[0], ua.x,  Vp[ic][0], M[0]);
            FMA_X2(M[1], ua.y,  Vp[ic][1], M[1]);
            FMA_X2(M[2], ub.x,  Vp[ic][2], M[2]);
            FMA_X2(M[3], ub.y,  Vp[ic][3], M[3]);
            FMA_X2(M[4], uc2.x, Vp[ic][4], M[4]);
            FMA_X2(M[5], uc2.y, Vp[ic][5], M[5]);
            FMA_X2(M[6], ud.x,  Vp[ic][6], M[6]);
            FMA_X2(M[7], ud.y,  Vp[ic][7], M[7]);
        }
        float m[16];
#pragma unroll
        for (int j = 0; j < 8; ++j) {
            unsigned lo, hi;
            UNPACK2(lo, hi, M[j]);
            m[2 * j]     = __uint_as_float(lo);
            m[2 * j + 1] = __uint_as_float(hi);
        }
        // output transform Y = A^T M A
        float q0[4], q1[4];
#pragma unroll
        for (int cix = 0; cix < 4; ++cix) {
            q0[cix] = m[cix] + m[4 + cix] + m[8 + cix];
            q1[cix] = m[4 + cix] - m[8 + cix] - m[12 + cix];
        }
        float y00 = q0[0] + q0[1] + q0[2];
        float y01 = q0[1] - q0[2] - q0[3];
        float y10 = q1[0] + q1[1] + q1[2];
        float y11 = q1[1] - q1[2] - q1[3];

        float inv = __ldg(&g_inv1[oc]);
        float bet = __ldg(&g_beta1[oc]);
        float mx = fmaxf(fmaxf(y00, y01), fmaxf(y10, y11));
        float mn = fminf(fminf(y00, y01), fminf(y10, y11));
        float z = (inv >= 0.f ? mx : mn) * inv + bet;
        bool sp = z > 1.0f;
        unsigned bal = __ballot_sync(0xffffffffu, sp);
        if (lane == 0 && bal) atomicAdd(&sc[0][oc], __popc(bal));
        if (edge) {
            unsigned bR0 = __ballot_sync(0xffffffffu, sp && (gpy == 0));
            unsigned bR1 = __ballot_sync(0xffffffffu, sp && (gpy == 127));
            unsigned bC0 = __ballot_sync(0xffffffffu, sp && (gpx == 0));
            unsigned bC1 = __ballot_sync(0xffffffffu, sp && (gpx == 127));
            if (lane == 0) {
                if (bR0) atomicAdd(&sc[1][oc], __popc(bR0));
                if (bR1) atomicAdd(&sc[2][oc], __popc(bR1));
                if (bC0) atomicAdd(&sc[3][oc], __popc(bC0));
                if (bC1) atomicAdd(&sc[4][oc], __popc(bC1));
            }
            if (sp) {  // corner bits (unique writer per corner; pre-zeroed)
                if (gpy == 0   && gpx == 0)        g_cnt[n][oc][5] = 1;
                else if (gpy == 0   && gpx == 127) g_cnt[n][oc][6] = 1;
                else if (gpy == 127 && gpx == 0)   g_cnt[n][oc][7] = 1;
                else if (gpy == 127 && gpx == 127) g_cnt[n][oc][8] = 1;
            }
        }
    }
    __syncthreads();
    if (tid < OC1) {
#pragma unroll
        for (int j = 0; j < 5; ++j) {
            int v = sc[j][tid];
            if (v) atomicAdd(&g_cnt[n][tid][j], v);
        }
    }
}

// ---------------------------------------------------------------------------
// stage B: analytic conv2-mean via T aggregates, BN2, spike -> g_s2
// ---------------------------------------------------------------------------
__global__ __launch_bounds__(256) void stageB_kernel(const float* __restrict__ w2) {
    __shared__ __align__(16) float sT[OC1 * 9];
    const int n = blockIdx.x, tid = threadIdx.x;
    const int lane = tid & 31, warp = tid >> 5;
    if (tid < OC1) {
        const int* c = g_cnt[n][tid];
        int S = c[0], Rf = c[1], Rl = c[2], Cf = c[3], Cl = c[4];
        int Re[3] = {Rl, 0, Rf};
        int Ce[3] = {Cl, 0, Cf};
        int Q[9]  = {c[8], 0, c[7],  0, 0, 0,  c[6], 0, c[5]};
#pragma unroll
        for (int k = 0; k < 9; ++k)
            sT[tid * 9 + k] = (float)(S - Re[k / 3] - Ce[k % 3] + Q[k]);
    }
    __syncthreads();
#pragma unroll 1
    for (int i = 0; i < 16; ++i) {
        const int o = warp * 16 + i;
        const float* wr = w2 + o * 576;
        float acc = 0.f;
#pragma unroll
        for (int t = 0; t < 18; ++t) {
            int j = t * 32 + lane;
            acc = fmaf(__ldg(&wr[j]), sT[j], acc);
        }
#pragma unroll
        for (int s = 16; s; s >>= 1) acc += __shfl_xor_sync(0xffffffffu, acc, s);
        if (lane == 0) {
            float z = acc * (1.f / 16384.f);
            z = z * g_inv2[o] + g_beta2[o];
            g_s2[n][o] = (z > 1.f) ? 1.f : 0.f;
        }
    }
}

// ---------------------------------------------------------------------------
// stage C: feat = |s0 - s1|, fc1+relu, fc2  -> out (32,5)
// ---------------------------------------------------------------------------
__global__ __launch_bounds__(256) void stageC_kernel(const float* __restrict__ fc1w,
                                                     const float* __restrict__ fc1b,
                                                     const float* __restrict__ fc2w,
                                                     const float* __restrict__ fc2b,
                                                     float* __restrict__ out) {
    __shared__ float f[128];
    __shared__ float h[64];
    const int n = blockIdx.x, tid = threadIdx.x;
    const int lane = tid & 31, warp = tid >> 5;
    if (tid < 128) f[tid] = fabsf(g_s2[n][tid] - g_s2[n + 32][tid]);
    __syncthreads();
#pragma unroll 1
    for (int i = 0; i < 8; ++i) {
        const int k = warp * 8 + i;
        const float* wr = fc1w + k * 128;
        float acc = 0.f;
#pragma unroll
        for (int t = 0; t < 4; ++t) {
            int j = t * 32 + lane;
            acc = fmaf(__ldg(&wr[j]), f[j], acc);
        }
#pragma unroll
        for (int s = 16; s; s >>= 1) acc += __shfl_xor_sync(0xffffffffu, acc, s);
        if (lane == 0) h[k] = fmaxf(acc + fc1b[k], 0.f);
    }
    __syncthreads();
    if (warp == 0) {
#pragma unroll 1
        for (int c = 0; c < 5; ++c) {
            const float* wr = fc2w + c * 64;
            float acc = fmaf(__ldg(&wr[lane]), h[lane], 0.f);
            acc = fmaf(__ldg(&wr[lane + 32]), h[lane + 32], acc);
#pragma unroll
            for (int s = 16; s; s >>= 1) acc += __shfl_xor_sync(0xffffffffu, acc, s);
            if (lane == 0) out[n * 5 + c] = acc + fc2b[c];
        }
    }
}

extern "C" void kernel_launch(void* const* d_in, const int* in_sizes, int n_in,
                              void* d_out, int out_size) {
    const float* x0   = (const float*)d_in[0];
    const float* x1   = (const float*)d_in[1];
    const float* w1   = (const float*)d_in[2];
    const float* b1g  = (const float*)d_in[3];
    const float* b1b  = (const float*)d_in[4];
    const float* b1m  = (const float*)d_in[5];
    const float* b1v  = (const float*)d_in[6];
    const float* w2   = (const float*)d_in[7];
    const float* b2g  = (const float*)d_in[8];
    const float* b2b  = (const float*)d_in[9];
    const float* b2m  = (const float*)d_in[10];
    const float* b2v  = (const float*)d_in[11];
    const float* fc1w = (const float*)d_in[12];
    const float* fc1b = (const float*)d_in[13];
    const float* fc2w = (const float*)d_in[14];
    const float* fc2b = (const float*)d_in[15];

    prep_kernel<<<32, 256>>>(w1, b1g, b1b, b1m, b1v, b2g, b2b, b2m, b2v);
    dim3 gridA(8, 16, 64);
    stageA_kernel<<<gridA, 128>>>(x0, x1);
    stageB_kernel<<<64, 256>>>(w2);
    stageC_kernel<<<32, 256>>>(fc1w, fc1b, fc2w, fc2b, (float*)d_out);
}